// round 13
// baseline (speedup 1.0000x reference)
#include <cuda_runtime.h>
#include <cuda_fp16.h>
#include <math.h>
#include <stdint.h>

#define NR   32768
#define PD   1024
#define HDD  1024
#define DD   2048

// ---------------- scratch ----------------
__device__ __half g_a1[(size_t)NR * DD];     // 128 MB: a1 (fp16)
__device__ __half g_xh[(size_t)NR * DD];     // 128 MB: [x|h] fp16
__device__ __half g_w1[(size_t)DD * DD];     // 8 MB  : W1 fp16
__device__ __half g_w2[(size_t)PD * DD];     // 4 MB  : W2 fp16
__device__ double g_musum[HDD];
__device__ double g_rs2;
__device__ double g_diffh;
__device__ double g_diffx;

__global__ void init_kernel() {
    int t = threadIdx.x + blockIdx.x * blockDim.x;
    if (t == 0) { g_rs2 = 0.0; g_diffh = 0.0; g_diffx = 0.0; }
    if (t < HDD) g_musum[t] = 0.0;
}

// ================= helpers =================
__device__ __forceinline__ uint32_t smem_u32(const void* p) {
    uint32_t a;
    asm("{ .reg .u64 t; cvta.to.shared.u64 t, %1; cvt.u32.u64 %0, t; }" : "=r"(a) : "l"(p));
    return a;
}
__device__ __forceinline__ void cp_async16(uint32_t saddr, const void* g) {
    asm volatile("cp.async.cg.shared.global [%0], [%1], 16;" :: "r"(saddr), "l"(g) : "memory");
}
#define CP_COMMIT()  asm volatile("cp.async.commit_group;" ::: "memory")
#define CP_WAIT1()   asm volatile("cp.async.wait_group 1;" ::: "memory")

__device__ __forceinline__ uint32_t sw128(uint32_t off) {
    return off ^ ((off >> 3) & 0x70);
}
__device__ __forceinline__ void ldsm4(uint32_t& r0, uint32_t& r1, uint32_t& r2, uint32_t& r3,
                                      uint32_t addr) {
    asm volatile("ldmatrix.sync.aligned.m8n8.x4.shared.b16 {%0,%1,%2,%3}, [%4];"
                 : "=r"(r0), "=r"(r1), "=r"(r2), "=r"(r3) : "r"(addr));
}
__device__ __forceinline__ void mma_f16(float* c, const uint32_t* a, const uint32_t* b) {
    asm volatile(
        "mma.sync.aligned.m16n8k16.row.col.f32.f16.f16.f32 "
        "{%0,%1,%2,%3}, {%4,%5,%6,%7}, {%8,%9}, {%0,%1,%2,%3};"
        : "+f"(c[0]), "+f"(c[1]), "+f"(c[2]), "+f"(c[3])
        : "r"(a[0]), "r"(a[1]), "r"(a[2]), "r"(a[3]), "r"(b[0]), "r"(b[1]));
}

// ================= prep_x: x -> fp16 low half of xh =================
__global__ void prep_x(const float* __restrict__ x, __half* __restrict__ xh) {
    const size_t g = (size_t)blockIdx.x * 256 + threadIdx.x;   // NR*256 float4s
    const size_t row = g >> 8, c = g & 255;
    float4 v = ((const float4*)x)[g];
    __half2* o = (__half2*)xh;
    o[row * 1024 + c * 2]     = __floats2half2_rn(v.x, v.y);
    o[row * 1024 + c * 2 + 1] = __floats2half2_rn(v.z, v.w);
}
__global__ void prep_round(const float* __restrict__ src, __half* __restrict__ dst) {
    const size_t g = (size_t)blockIdx.x * 256 + threadIdx.x;
    float4 v = ((const float4*)src)[g];
    ((__half2*)dst)[g * 2]     = __floats2half2_rn(v.x, v.y);
    ((__half2*)dst)[g * 2 + 1] = __floats2half2_rn(v.z, v.w);
}

// ================= h_stats: one pass over h =================
// Per warp: rows [a, a+32) owned (+1 halo). Emits fp16 h into xh high half,
// row sums -> g_rs2, ||h[i+1]-h[i]||^2 -> g_diffh, column sums -> g_musum.
__global__ __launch_bounds__(256) void h_stats(const float* __restrict__ h,
                                               __half* __restrict__ xh) {
    __shared__ float scs[HDD];
    const int tid  = threadIdx.x;
    const int wid  = tid >> 5;
    const int lane = tid & 31;
    const int a = blockIdx.x * 256 + wid * 32;

    scs[tid * 4 + 0] = 0.f; scs[tid * 4 + 1] = 0.f;
    scs[tid * 4 + 2] = 0.f; scs[tid * 4 + 3] = 0.f;
    __syncthreads();

    float cur[32], prev[32], csum[32];
#pragma unroll
    for (int j = 0; j < 32; ++j) csum[j] = 0.f;

    double rs2_loc = 0.0, dh_loc = 0.0;

    for (int r = a; r < a + 32; ++r) {
        float rsum = 0.f;
#pragma unroll
        for (int it2 = 0; it2 < 8; ++it2) {
            const int col = it2 * 128 + lane * 4;
            float4 v = *(const float4*)&h[(size_t)r * HDD + col];
            cur[it2 * 4 + 0] = v.x; cur[it2 * 4 + 1] = v.y;
            cur[it2 * 4 + 2] = v.z; cur[it2 * 4 + 3] = v.w;
            csum[it2 * 4 + 0] += v.x; csum[it2 * 4 + 1] += v.y;
            csum[it2 * 4 + 2] += v.z; csum[it2 * 4 + 3] += v.w;
            rsum += (v.x + v.y) + (v.z + v.w);
            __half2* o = (__half2*)&xh[(size_t)r * DD + PD + col];
            o[0] = __floats2half2_rn(v.x, v.y);
            o[1] = __floats2half2_rn(v.z, v.w);
        }
#pragma unroll
        for (int o = 16; o; o >>= 1) rsum += __shfl_down_sync(0xffffffffu, rsum, o);
        if (lane == 0 && r < NR - 1) rs2_loc += (double)rsum * (double)rsum;

        if (r > a) {
            float d2 = 0.f;
#pragma unroll
            for (int j = 0; j < 32; ++j) {
                float d = cur[j] - prev[j];
                d2 += d * d;
            }
#pragma unroll
            for (int o = 16; o; o >>= 1) d2 += __shfl_down_sync(0xffffffffu, d2, o);
            if (lane == 0) dh_loc += (double)d2;
        }
#pragma unroll
        for (int j = 0; j < 32; ++j) prev[j] = cur[j];
    }

    if (a + 32 < NR) {                       // halo: diff for row a+31
        float d2 = 0.f;
#pragma unroll
        for (int it2 = 0; it2 < 8; ++it2) {
            const int col = it2 * 128 + lane * 4;
            float4 v = *(const float4*)&h[(size_t)(a + 32) * HDD + col];
            float d;
            d = v.x - prev[it2 * 4 + 0]; d2 += d * d;
            d = v.y - prev[it2 * 4 + 1]; d2 += d * d;
            d = v.z - prev[it2 * 4 + 2]; d2 += d * d;
            d = v.w - prev[it2 * 4 + 3]; d2 += d * d;
        }
#pragma unroll
        for (int o = 16; o; o >>= 1) d2 += __shfl_down_sync(0xffffffffu, d2, o);
        if (lane == 0) dh_loc += (double)d2;
    }

    if (lane == 0) {
        atomicAdd(&g_rs2, rs2_loc);
        atomicAdd(&g_diffh, dh_loc);
    }

    // column sums: per-warp regs -> block smem -> global
#pragma unroll
    for (int it2 = 0; it2 < 8; ++it2) {
        const int col = it2 * 128 + lane * 4;
        atomicAdd(&scs[col + 0], csum[it2 * 4 + 0]);
        atomicAdd(&scs[col + 1], csum[it2 * 4 + 1]);
        atomicAdd(&scs[col + 2], csum[it2 * 4 + 2]);
        atomicAdd(&scs[col + 3], csum[it2 * 4 + 3]);
    }
    __syncthreads();
#pragma unroll
    for (int j = 0; j < 4; ++j) {
        const int c = tid * 4 + j;
        atomicAdd(&g_musum[c], (double)scs[c]);
    }
}

// ================= fp16 mma.sync GEMM =================
// C[m,n] = relu(sum_k A[m,k]*B[n,k] + bias[n]);  A,B fp16, fp32 accumulate.
// CTA tile 256x128, BK=64, 512 threads (16 warps, 4Mx4N), warp tile 64x32.
// FUSE_DX: accumulate ||C - (X[i+1]-X[i])||^2 into g_diffx during epilogue.
#define BM 256
#define BN 128
#define BK 64
#define NSTG 3
#define A_BYTES 32768                     // 256 rows x 128B
#define B_BYTES 16384                     // 128 rows x 128B
#define STAGE_BYTES (A_BYTES + B_BYTES)   // 49152
#define GEMM_SMEM (NSTG * STAGE_BYTES)    // 147456

__device__ __forceinline__ void load_stage(
    int j, int tid, int bm, int bn,
    const __half* __restrict__ A, int lda,
    const __half* __restrict__ B, int ldb, uint32_t stg0)
{
    const uint32_t sA = stg0 + (j % NSTG) * STAGE_BYTES;
    const uint32_t sB = sA + A_BYTES;
    const int kg = j << 6;                        // 64 halves per stage
#pragma unroll
    for (int i = 0; i < 4; ++i) {                 // A: 2048 16B-chunks / 512 thr
        int q = tid + (i << 9);
        int row = q >> 3, c16 = q & 7;
        cp_async16(sA + sw128(row * 128 + c16 * 16),
                   A + (size_t)(bm + row) * lda + kg + (c16 << 3));
    }
#pragma unroll
    for (int i = 0; i < 2; ++i) {                 // B: 1024 chunks
        int q = tid + (i << 9);
        int row = q >> 3, c16 = q & 7;
        cp_async16(sB + sw128(row * 128 + c16 * 16),
                   B + (size_t)(bn + row) * ldb + kg + (c16 << 3));
    }
}

template<bool HALF_OUT, bool FUSE_DX>
__global__ __launch_bounds__(512, 1) void gemm_f16(
    const __half* __restrict__ A, int lda,
    const __half* __restrict__ B, const float* __restrict__ bias,
    void* __restrict__ Cv, int Ncols, int K,
    const float* __restrict__ Xp)
{
    extern __shared__ char smem[];
    const int tid  = threadIdx.x;
    const int wid  = tid >> 5;
    const int lane = tid & 31;
    const int bm = blockIdx.y << 8;       // BM=256
    const int bn = blockIdx.x << 7;       // BN=128
    const uint32_t stg0 = smem_u32(smem);

    const int wm = (wid & 3) << 6;        // warp M offset: 0..192
    const int wn = (wid >> 2) << 5;       // warp N offset: 0..96

    float acc[4][4][4];
#pragma unroll
    for (int i = 0; i < 4; ++i)
#pragma unroll
        for (int j = 0; j < 4; ++j)
#pragma unroll
            for (int r = 0; r < 4; ++r) acc[i][j][r] = 0.f;

    const int nk = K >> 6;                // 32 iterations of BK=64
    load_stage(0, tid, bm, bn, A, lda, B, K, stg0); CP_COMMIT();
    load_stage(1, tid, bm, bn, A, lda, B, K, stg0); CP_COMMIT();

    const int a_row_l = lane & 15;
    const int a_chk_l = lane >> 4;
    const int b_row_l = (lane & 7) + ((lane >> 4) & 1) * 8;
    const int b_chk_l = (lane >> 3) & 1;

    for (int it = 0; it < nk; ++it) {
        CP_WAIT1();
        __syncthreads();

        const int jn = it + 2;
        if (jn < nk) load_stage(jn, tid, bm, bn, A, lda, B, K, stg0);
        CP_COMMIT();

        const uint32_t sA = stg0 + (it % NSTG) * STAGE_BYTES;
        const uint32_t sB = sA + A_BYTES;

#pragma unroll
        for (int q = 0; q < 4; ++q) {
            uint32_t af[4][4], bf[2][4];
#pragma unroll
            for (int t = 0; t < 4; ++t) {
                const int row = wm + t * 16 + a_row_l;
                ldsm4(af[t][0], af[t][1], af[t][2], af[t][3],
                      sA + sw128(row * 128 + q * 32 + a_chk_l * 16));
            }
#pragma unroll
            for (int p = 0; p < 2; ++p) {
                const int row = wn + p * 16 + b_row_l;
                ldsm4(bf[p][0], bf[p][1], bf[p][2], bf[p][3],
                      sB + sw128(row * 128 + q * 32 + b_chk_l * 16));
            }
#pragma unroll
            for (int t = 0; t < 4; ++t)
#pragma unroll
                for (int nt = 0; nt < 4; ++nt)
                    mma_f16(acc[t][nt], af[t], &bf[nt >> 1][(nt & 1) * 2]);
        }
        __syncthreads();
    }

    // -------- epilogue: bias + relu (+ fused diffx) --------
    const int g   = lane >> 2;
    const int ctg = lane & 3;
    float2 bv[4];
#pragma unroll
    for (int nt = 0; nt < 4; ++nt)
        bv[nt] = *(const float2*)&bias[bn + wn + nt * 8 + ctg * 2];

    float dacc = 0.f;

#pragma unroll
    for (int t = 0; t < 4; ++t) {
        const int r0 = bm + wm + t * 16 + g;
#pragma unroll
        for (int nt = 0; nt < 4; ++nt) {
            const int col = bn + wn + nt * 8 + ctg * 2;
            float v00 = fmaxf(acc[t][nt][0] + bv[nt].x, 0.f);
            float v01 = fmaxf(acc[t][nt][1] + bv[nt].y, 0.f);
            float v10 = fmaxf(acc[t][nt][2] + bv[nt].x, 0.f);
            float v11 = fmaxf(acc[t][nt][3] + bv[nt].y, 0.f);
            if (HALF_OUT) {
                __half* C = (__half*)Cv;
                *(__half2*)&C[(size_t)r0 * Ncols + col]       = __floats2half2_rn(v00, v01);
                *(__half2*)&C[(size_t)(r0 + 8) * Ncols + col] = __floats2half2_rn(v10, v11);
            } else {
                float* C = (float*)Cv;
                *(float2*)&C[(size_t)r0 * Ncols + col]       = make_float2(v00, v01);
                *(float2*)&C[(size_t)(r0 + 8) * Ncols + col] = make_float2(v10, v11);
            }
            if (FUSE_DX) {
                if (r0 < NR - 1) {
                    float2 x0 = *(const float2*)&Xp[(size_t)r0 * PD + col];
                    float2 x1 = *(const float2*)&Xp[(size_t)(r0 + 1) * PD + col];
                    float d0 = v00 - (x1.x - x0.x);
                    float d1 = v01 - (x1.y - x0.y);
                    dacc += d0 * d0 + d1 * d1;
                }
                if (r0 + 8 < NR - 1) {
                    float2 x0 = *(const float2*)&Xp[(size_t)(r0 + 8) * PD + col];
                    float2 x1 = *(const float2*)&Xp[(size_t)(r0 + 9) * PD + col];
                    float d0 = v10 - (x1.x - x0.x);
                    float d1 = v11 - (x1.y - x0.y);
                    dacc += d0 * d0 + d1 * d1;
                }
            }
        }
    }

    if (FUSE_DX) {
#pragma unroll
        for (int o = 16; o; o >>= 1) dacc += __shfl_down_sync(0xffffffffu, dacc, o);
        __syncthreads();                       // stage smem no longer needed
        float* red = (float*)smem;
        if (lane == 0) red[wid] = dacc;
        __syncthreads();
        if (tid == 0) {
            float s = 0.f;
#pragma unroll
            for (int i = 0; i < 16; ++i) s += red[i];
            atomicAdd(&g_diffx, (double)s);
        }
    }
}

// ================= finalize =================
__global__ void finalize_kernel(float* __restrict__ out_scalars) {
    const int t = threadIdx.x;
    double mu = g_musum[t] * (1.0 / (double)NR);
    double a = mu, b = mu * mu;
#pragma unroll
    for (int o = 16; o; o >>= 1) {
        a += __shfl_down_sync(0xffffffffu, a, o);
        b += __shfl_down_sync(0xffffffffu, b, o);
    }
    __shared__ double pa[32], pb[32];
    const int w = t >> 5, l = t & 31;
    if (l == 0) { pa[w] = a; pb[w] = b; }
    __syncthreads();
    if (w == 0) {
        a = pa[l];
        b = pb[l];
#pragma unroll
        for (int o = 16; o; o >>= 1) {
            a += __shfl_down_sync(0xffffffffu, a, o);
            b += __shfl_down_sync(0xffffffffu, b, o);
        }
        if (t == 0) {
            const double smu = a, mumu = b;
            const double hd = (double)HDD, nm1 = (double)(NR - 1), eps = 1e-8;
            const double s = g_rs2 / nm1 / (hd * hd);
            const double loss1 = sqrt(g_diffx) / nm1 + sqrt(g_diffh) / nm1;
            const double trS = hd * s - mumu;
            const double detM = (1.0 + s * hd / eps) * (1.0 - mumu / eps)
                              + s * smu * smu / (eps * eps);
            const double logabsdet = hd * log(eps) + log(fabs(detM));
            const double loss = loss1 + 0.5 * (mumu + trS - hd - logabsdet);
            out_scalars[0] = (float)loss1;
            out_scalars[1] = (float)loss;
        }
    }
}

// ================= launch =================
extern "C" void kernel_launch(void* const* d_in, const int* in_sizes, int n_in,
                              void* d_out, int out_size) {
    const float* x  = (const float*)d_in[0];
    const float* h  = (const float*)d_in[1];
    const float* W1 = (const float*)d_in[2];
    const float* b1 = (const float*)d_in[3];
    const float* W2 = (const float*)d_in[4];
    const float* b2 = (const float*)d_in[5];

    float* out     = (float*)d_out;
    float* f       = out;
    float* scalars = out + (size_t)NR * PD;

    __half *a1, *xh, *w1, *w2;
    cudaGetSymbolAddress((void**)&a1, g_a1);
    cudaGetSymbolAddress((void**)&xh, g_xh);
    cudaGetSymbolAddress((void**)&w1, g_w1);
    cudaGetSymbolAddress((void**)&w2, g_w2);

    cudaFuncSetAttribute(gemm_f16<true,  false>, cudaFuncAttributeMaxDynamicSharedMemorySize, GEMM_SMEM);
    cudaFuncSetAttribute(gemm_f16<false, true>,  cudaFuncAttributeMaxDynamicSharedMemorySize, GEMM_SMEM);

    init_kernel<<<4, 256>>>();

    // prep + fused h statistics
    prep_x<<<NR, 256>>>(x, xh);
    h_stats<<<NR / 256, 256>>>(h, xh);
    prep_round<<<(DD * DD / 4) / 256, 256>>>(W1, w1);
    prep_round<<<(PD * DD / 4) / 256, 256>>>(W2, w2);

    // GEMM1: a1 = relu(xh @ W1^T + b1), fp16 output
    gemm_f16<true, false><<<dim3(DD / BN, NR / BM), 512, GEMM_SMEM>>>(
        xh, DD, w1, b1, a1, DD, DD, nullptr);

    // GEMM2: f = relu(a1 @ W2^T + b2), fp32 output + fused diffx
    gemm_f16<false, true><<<dim3(PD / BN, NR / BM), 512, GEMM_SMEM>>>(
        a1, DD, w2, b2, f, PD, DD, x);

    finalize_kernel<<<1, 1024>>>(scalars);
}

// round 15
// speedup vs baseline: 1.0161x; 1.0161x over previous
#include <cuda_runtime.h>
#include <cuda_fp16.h>
#include <math.h>
#include <stdint.h>

#define NR   32768
#define PD   1024
#define HDD  1024
#define DD   2048

// ---------------- scratch ----------------
__device__ __half g_a1[(size_t)NR * DD];     // 128 MB: a1 (fp16)
__device__ __half g_xh[(size_t)NR * DD];     // 128 MB: [x|h] fp16
__device__ __half g_w1[(size_t)DD * DD];     // 8 MB  : W1 fp16
__device__ __half g_w2[(size_t)PD * DD];     // 4 MB  : W2 fp16
__device__ double g_musum[HDD];
__device__ double g_rs2;
__device__ double g_diffh;
__device__ double g_diffx;

__global__ void init_kernel() {
    int t = threadIdx.x + blockIdx.x * blockDim.x;
    if (t == 0) { g_rs2 = 0.0; g_diffh = 0.0; g_diffx = 0.0; }
    if (t < HDD) g_musum[t] = 0.0;
}

// ================= helpers =================
__device__ __forceinline__ uint32_t smem_u32(const void* p) {
    uint32_t a;
    asm("{ .reg .u64 t; cvta.to.shared.u64 t, %1; cvt.u32.u64 %0, t; }" : "=r"(a) : "l"(p));
    return a;
}
__device__ __forceinline__ void cp_async16(uint32_t saddr, const void* g) {
    asm volatile("cp.async.cg.shared.global [%0], [%1], 16;" :: "r"(saddr), "l"(g) : "memory");
}
#define CP_COMMIT()  asm volatile("cp.async.commit_group;" ::: "memory")
#define CP_WAIT1()   asm volatile("cp.async.wait_group 1;" ::: "memory")

__device__ __forceinline__ uint32_t sw128(uint32_t off) {
    return off ^ ((off >> 3) & 0x70);
}
__device__ __forceinline__ void ldsm4(uint32_t& r0, uint32_t& r1, uint32_t& r2, uint32_t& r3,
                                      uint32_t addr) {
    asm volatile("ldmatrix.sync.aligned.m8n8.x4.shared.b16 {%0,%1,%2,%3}, [%4];"
                 : "=r"(r0), "=r"(r1), "=r"(r2), "=r"(r3) : "r"(addr));
}
__device__ __forceinline__ void mma_f16(float* c, const uint32_t* a, const uint32_t* b) {
    asm volatile(
        "mma.sync.aligned.m16n8k16.row.col.f32.f16.f16.f32 "
        "{%0,%1,%2,%3}, {%4,%5,%6,%7}, {%8,%9}, {%0,%1,%2,%3};"
        : "+f"(c[0]), "+f"(c[1]), "+f"(c[2]), "+f"(c[3])
        : "r"(a[0]), "r"(a[1]), "r"(a[2]), "r"(a[3]), "r"(b[0]), "r"(b[1]));
}

// ================= merged prep =================
// Block ranges (h_stats first — longest-running blocks start earliest):
//   [0, 128)                : h_stats  (h -> xh high half + stats)
//   [128, 128+4096)         : x -> fp16 xh low half
//   [4224, 4224+1024)       : W1 -> fp16
//   [5248, 5248+512)        : W2 -> fp16
#define HBLK  128
#define XBLK  4096
#define W1BLK 1024
#define W2BLK 512
#define PREP_GRID (HBLK + XBLK + W1BLK + W2BLK)

__global__ __launch_bounds__(256) void prep_all(
    const float* __restrict__ x, const float* __restrict__ h,
    const float* __restrict__ W1, const float* __restrict__ W2,
    __half* __restrict__ xh, __half* __restrict__ w1, __half* __restrict__ w2)
{
    __shared__ float scs[HDD];
    const int tid  = threadIdx.x;
    const int blk  = blockIdx.x;

    if (blk >= HBLK) {
        // ---- streaming fp32 -> fp16 conversions ----
        const float* src;
        __half* dst;
        size_t base;   // in float4 units
        if (blk < HBLK + XBLK) {
            // x into interleaved xh low half: 2048 float4s per block
            const size_t b = (size_t)(blk - HBLK) * 2048;
#pragma unroll
            for (int j = 0; j < 8; ++j) {
                const size_t idx = b + tid + j * 256;
                const size_t row = idx >> 8, c = idx & 255;
                float4 v = ((const float4*)x)[idx];
                __half2* o = (__half2*)xh;
                o[row * 1024 + c * 2]     = __floats2half2_rn(v.x, v.y);
                o[row * 1024 + c * 2 + 1] = __floats2half2_rn(v.z, v.w);
            }
            return;
        } else if (blk < HBLK + XBLK + W1BLK) {
            src = W1; dst = w1;
            base = (size_t)(blk - HBLK - XBLK) * 1024;
        } else {
            src = W2; dst = w2;
            base = (size_t)(blk - HBLK - XBLK - W1BLK) * 1024;
        }
#pragma unroll
        for (int j = 0; j < 4; ++j) {
            const size_t idx = base + tid + j * 256;
            float4 v = ((const float4*)src)[idx];
            ((__half2*)dst)[idx * 2]     = __floats2half2_rn(v.x, v.y);
            ((__half2*)dst)[idx * 2 + 1] = __floats2half2_rn(v.z, v.w);
        }
        return;
    }

    // ---- h_stats branch (blocks [0, 128)) ----
    const int wid  = tid >> 5;
    const int lane = tid & 31;
    const int a = blk * 256 + wid * 32;

    scs[tid * 4 + 0] = 0.f; scs[tid * 4 + 1] = 0.f;
    scs[tid * 4 + 2] = 0.f; scs[tid * 4 + 3] = 0.f;
    __syncthreads();

    float cur[32], prev[32], csum[32];
#pragma unroll
    for (int j = 0; j < 32; ++j) csum[j] = 0.f;

    double rs2_loc = 0.0, dh_loc = 0.0;

    for (int r = a; r < a + 32; ++r) {
        float rsum = 0.f;
#pragma unroll
        for (int it2 = 0; it2 < 8; ++it2) {
            const int col = it2 * 128 + lane * 4;
            float4 v = *(const float4*)&h[(size_t)r * HDD + col];
            cur[it2 * 4 + 0] = v.x; cur[it2 * 4 + 1] = v.y;
            cur[it2 * 4 + 2] = v.z; cur[it2 * 4 + 3] = v.w;
            csum[it2 * 4 + 0] += v.x; csum[it2 * 4 + 1] += v.y;
            csum[it2 * 4 + 2] += v.z; csum[it2 * 4 + 3] += v.w;
            rsum += (v.x + v.y) + (v.z + v.w);
            __half2* o = (__half2*)&xh[(size_t)r * DD + PD + col];
            o[0] = __floats2half2_rn(v.x, v.y);
            o[1] = __floats2half2_rn(v.z, v.w);
        }
#pragma unroll
        for (int o = 16; o; o >>= 1) rsum += __shfl_down_sync(0xffffffffu, rsum, o);
        if (lane == 0 && r < NR - 1) rs2_loc += (double)rsum * (double)rsum;

        if (r > a) {
            float d2 = 0.f;
#pragma unroll
            for (int j = 0; j < 32; ++j) {
                float d = cur[j] - prev[j];
                d2 += d * d;
            }
#pragma unroll
            for (int o = 16; o; o >>= 1) d2 += __shfl_down_sync(0xffffffffu, d2, o);
            if (lane == 0) dh_loc += (double)d2;
        }
#pragma unroll
        for (int j = 0; j < 32; ++j) prev[j] = cur[j];
    }

    if (a + 32 < NR) {                       // halo: diff for row a+31
        float d2 = 0.f;
#pragma unroll
        for (int it2 = 0; it2 < 8; ++it2) {
            const int col = it2 * 128 + lane * 4;
            float4 v = *(const float4*)&h[(size_t)(a + 32) * HDD + col];
            float d;
            d = v.x - prev[it2 * 4 + 0]; d2 += d * d;
            d = v.y - prev[it2 * 4 + 1]; d2 += d * d;
            d = v.z - prev[it2 * 4 + 2]; d2 += d * d;
            d = v.w - prev[it2 * 4 + 3]; d2 += d * d;
        }
#pragma unroll
        for (int o = 16; o; o >>= 1) d2 += __shfl_down_sync(0xffffffffu, d2, o);
        if (lane == 0) dh_loc += (double)d2;
    }

    if (lane == 0) {
        atomicAdd(&g_rs2, rs2_loc);
        atomicAdd(&g_diffh, dh_loc);
    }

#pragma unroll
    for (int it2 = 0; it2 < 8; ++it2) {
        const int col = it2 * 128 + lane * 4;
        atomicAdd(&scs[col + 0], csum[it2 * 4 + 0]);
        atomicAdd(&scs[col + 1], csum[it2 * 4 + 1]);
        atomicAdd(&scs[col + 2], csum[it2 * 4 + 2]);
        atomicAdd(&scs[col + 3], csum[it2 * 4 + 3]);
    }
    __syncthreads();
#pragma unroll
    for (int j = 0; j < 4; ++j) {
        const int c = tid * 4 + j;
        atomicAdd(&g_musum[c], (double)scs[c]);
    }
}

// ================= fp16 mma.sync GEMM (proven R10/R13) =================
#define BM 256
#define BN 128
#define BK 64
#define NSTG 3
#define A_BYTES 32768
#define B_BYTES 16384
#define STAGE_BYTES (A_BYTES + B_BYTES)   // 49152
#define GEMM_SMEM (NSTG * STAGE_BYTES)    // 147456

__device__ __forceinline__ void load_stage(
    int j, int tid, int bm, int bn,
    const __half* __restrict__ A, int lda,
    const __half* __restrict__ B, int ldb, uint32_t stg0)
{
    const uint32_t sA = stg0 + (j % NSTG) * STAGE_BYTES;
    const uint32_t sB = sA + A_BYTES;
    const int kg = j << 6;
#pragma unroll
    for (int i = 0; i < 4; ++i) {
        int q = tid + (i << 9);
        int row = q >> 3, c16 = q & 7;
        cp_async16(sA + sw128(row * 128 + c16 * 16),
                   A + (size_t)(bm + row) * lda + kg + (c16 << 3));
    }
#pragma unroll
    for (int i = 0; i < 2; ++i) {
        int q = tid + (i << 9);
        int row = q >> 3, c16 = q & 7;
        cp_async16(sB + sw128(row * 128 + c16 * 16),
                   B + (size_t)(bn + row) * ldb + kg + (c16 << 3));
    }
}

template<bool HALF_OUT, bool FUSE_DX>
__global__ __launch_bounds__(512, 1) void gemm_f16(
    const __half* __restrict__ A, int lda,
    const __half* __restrict__ B, const float* __restrict__ bias,
    void* __restrict__ Cv, int Ncols, int K,
    const float* __restrict__ Xp)
{
    extern __shared__ char smem[];
    const int tid  = threadIdx.x;
    const int wid  = tid >> 5;
    const int lane = tid & 31;
    const int bm = blockIdx.y << 8;
    const int bn = blockIdx.x << 7;
    const uint32_t stg0 = smem_u32(smem);

    const int wm = (wid & 3) << 6;
    const int wn = (wid >> 2) << 5;

    float acc[4][4][4];
#pragma unroll
    for (int i = 0; i < 4; ++i)
#pragma unroll
        for (int j = 0; j < 4; ++j)
#pragma unroll
            for (int r = 0; r < 4; ++r) acc[i][j][r] = 0.f;

    const int nk = K >> 6;
    load_stage(0, tid, bm, bn, A, lda, B, K, stg0); CP_COMMIT();
    load_stage(1, tid, bm, bn, A, lda, B, K, stg0); CP_COMMIT();

    const int a_row_l = lane & 15;
    const int a_chk_l = lane >> 4;
    const int b_row_l = (lane & 7) + ((lane >> 4) & 1) * 8;
    const int b_chk_l = (lane >> 3) & 1;

    for (int it = 0; it < nk; ++it) {
        CP_WAIT1();
        __syncthreads();

        const int jn = it + 2;
        if (jn < nk) load_stage(jn, tid, bm, bn, A, lda, B, K, stg0);
        CP_COMMIT();

        const uint32_t sA = stg0 + (it % NSTG) * STAGE_BYTES;
        const uint32_t sB = sA + A_BYTES;

#pragma unroll
        for (int q = 0; q < 4; ++q) {
            uint32_t af[4][4], bf[2][4];
#pragma unroll
            for (int t = 0; t < 4; ++t) {
                const int row = wm + t * 16 + a_row_l;
                ldsm4(af[t][0], af[t][1], af[t][2], af[t][3],
                      sA + sw128(row * 128 + q * 32 + a_chk_l * 16));
            }
#pragma unroll
            for (int p = 0; p < 2; ++p) {
                const int row = wn + p * 16 + b_row_l;
                ldsm4(bf[p][0], bf[p][1], bf[p][2], bf[p][3],
                      sB + sw128(row * 128 + q * 32 + b_chk_l * 16));
            }
#pragma unroll
            for (int t = 0; t < 4; ++t)
#pragma unroll
                for (int nt = 0; nt < 4; ++nt)
                    mma_f16(acc[t][nt], af[t], &bf[nt >> 1][(nt & 1) * 2]);
        }
        __syncthreads();
    }

    const int g   = lane >> 2;
    const int ctg = lane & 3;
    float2 bv[4];
#pragma unroll
    for (int nt = 0; nt < 4; ++nt)
        bv[nt] = *(const float2*)&bias[bn + wn + nt * 8 + ctg * 2];

    float dacc = 0.f;

#pragma unroll
    for (int t = 0; t < 4; ++t) {
        const int r0 = bm + wm + t * 16 + g;
#pragma unroll
        for (int nt = 0; nt < 4; ++nt) {
            const int col = bn + wn + nt * 8 + ctg * 2;
            float v00 = fmaxf(acc[t][nt][0] + bv[nt].x, 0.f);
            float v01 = fmaxf(acc[t][nt][1] + bv[nt].y, 0.f);
            float v10 = fmaxf(acc[t][nt][2] + bv[nt].x, 0.f);
            float v11 = fmaxf(acc[t][nt][3] + bv[nt].y, 0.f);
            if (HALF_OUT) {
                __half* C = (__half*)Cv;
                *(__half2*)&C[(size_t)r0 * Ncols + col]       = __floats2half2_rn(v00, v01);
                *(__half2*)&C[(size_t)(r0 + 8) * Ncols + col] = __floats2half2_rn(v10, v11);
            } else {
                float* C = (float*)Cv;
                *(float2*)&C[(size_t)r0 * Ncols + col]       = make_float2(v00, v01);
                *(float2*)&C[(size_t)(r0 + 8) * Ncols + col] = make_float2(v10, v11);
            }
            if (FUSE_DX) {
                if (r0 < NR - 1) {
                    float2 x0 = *(const float2*)&Xp[(size_t)r0 * PD + col];
                    float2 x1 = *(const float2*)&Xp[(size_t)(r0 + 1) * PD + col];
                    float d0 = v00 - (x1.x - x0.x);
                    float d1 = v01 - (x1.y - x0.y);
                    dacc += d0 * d0 + d1 * d1;
                }
                if (r0 + 8 < NR - 1) {
                    float2 x0 = *(const float2*)&Xp[(size_t)(r0 + 8) * PD + col];
                    float2 x1 = *(const float2*)&Xp[(size_t)(r0 + 9) * PD + col];
                    float d0 = v10 - (x1.x - x0.x);
                    float d1 = v11 - (x1.y - x0.y);
                    dacc += d0 * d0 + d1 * d1;
                }
            }
        }
    }

    if (FUSE_DX) {
#pragma unroll
        for (int o = 16; o; o >>= 1) dacc += __shfl_down_sync(0xffffffffu, dacc, o);
        __syncthreads();
        float* red = (float*)smem;
        if (lane == 0) red[wid] = dacc;
        __syncthreads();
        if (tid == 0) {
            float s = 0.f;
#pragma unroll
            for (int i = 0; i < 16; ++i) s += red[i];
            atomicAdd(&g_diffx, (double)s);
        }
    }
}

// ================= finalize =================
__global__ void finalize_kernel(float* __restrict__ out_scalars) {
    const int t = threadIdx.x;
    double mu = g_musum[t] * (1.0 / (double)NR);
    double a = mu, b = mu * mu;
#pragma unroll
    for (int o = 16; o; o >>= 1) {
        a += __shfl_down_sync(0xffffffffu, a, o);
        b += __shfl_down_sync(0xffffffffu, b, o);
    }
    __shared__ double pa[32], pb[32];
    const int w = t >> 5, l = t & 31;
    if (l == 0) { pa[w] = a; pb[w] = b; }
    __syncthreads();
    if (w == 0) {
        a = pa[l];
        b = pb[l];
#pragma unroll
        for (int o = 16; o; o >>= 1) {
            a += __shfl_down_sync(0xffffffffu, a, o);
            b += __shfl_down_sync(0xffffffffu, b, o);
        }
        if (t == 0) {
            const double smu = a, mumu = b;
            const double hd = (double)HDD, nm1 = (double)(NR - 1), eps = 1e-8;
            const double s = g_rs2 / nm1 / (hd * hd);
            const double loss1 = sqrt(g_diffx) / nm1 + sqrt(g_diffh) / nm1;
            const double trS = hd * s - mumu;
            const double detM = (1.0 + s * hd / eps) * (1.0 - mumu / eps)
                              + s * smu * smu / (eps * eps);
            const double logabsdet = hd * log(eps) + log(fabs(detM));
            const double loss = loss1 + 0.5 * (mumu + trS - hd - logabsdet);
            out_scalars[0] = (float)loss1;
            out_scalars[1] = (float)loss;
        }
    }
}

// ================= launch =================
extern "C" void kernel_launch(void* const* d_in, const int* in_sizes, int n_in,
                              void* d_out, int out_size) {
    const float* x  = (const float*)d_in[0];
    const float* h  = (const float*)d_in[1];
    const float* W1 = (const float*)d_in[2];
    const float* b1 = (const float*)d_in[3];
    const float* W2 = (const float*)d_in[4];
    const float* b2 = (const float*)d_in[5];

    float* out     = (float*)d_out;
    float* f       = out;
    float* scalars = out + (size_t)NR * PD;

    __half *a1, *xh, *w1, *w2;
    cudaGetSymbolAddress((void**)&a1, g_a1);
    cudaGetSymbolAddress((void**)&xh, g_xh);
    cudaGetSymbolAddress((void**)&w1, g_w1);
    cudaGetSymbolAddress((void**)&w2, g_w2);

    cudaFuncSetAttribute(gemm_f16<true,  false>, cudaFuncAttributeMaxDynamicSharedMemorySize, GEMM_SMEM);
    cudaFuncSetAttribute(gemm_f16<false, true>,  cudaFuncAttributeMaxDynamicSharedMemorySize, GEMM_SMEM);

    init_kernel<<<4, 256>>>();

    // merged prep: x/h/W1/W2 conversions + h statistics, one launch
    prep_all<<<PREP_GRID, 256>>>(x, h, W1, W2, xh, w1, w2);

    // GEMM1: a1 = relu(xh @ W1^T + b1), fp16 output
    gemm_f16<true, false><<<dim3(DD / BN, NR / BM), 512, GEMM_SMEM>>>(
        xh, DD, w1, b1, a1, DD, DD, nullptr);

    // GEMM2: f = relu(a1 @ W2^T + b2), fp32 output + fused diffx
    gemm_f16<false, true><<<dim3(PD / BN, NR / BM), 512, GEMM_SMEM>>>(
        a1, DD, w2, b2, f, PD, DD, x);

    finalize_kernel<<<1, 1024>>>(scalars);
}

// round 17
// speedup vs baseline: 1.0951x; 1.0778x over previous
#include <cuda_runtime.h>
#include <cuda_fp16.h>
#include <math.h>
#include <stdint.h>

#define NR   32768
#define PD   1024
#define HDD  1024
#define DD   2048

// ---------------- scratch ----------------
__device__ __half g_a1[(size_t)NR * DD];     // 128 MB: a1 (fp16)
__device__ __half g_xh[(size_t)NR * DD];     // 128 MB: [x|h] fp16
__device__ __half g_w1[(size_t)DD * DD];     // 8 MB  : W1 fp16
__device__ __half g_w2[(size_t)PD * DD];     // 4 MB  : W2 fp16
__device__ double g_musum[HDD];
__device__ double g_rs2;
__device__ double g_diffh;
__device__ double g_diffx;

__global__ void init_kernel() {
    int t = threadIdx.x + blockIdx.x * blockDim.x;
    if (t == 0) { g_rs2 = 0.0; g_diffh = 0.0; g_diffx = 0.0; }
    if (t < HDD) g_musum[t] = 0.0;
}

// ================= helpers =================
__device__ __forceinline__ uint32_t smem_u32(const void* p) {
    uint32_t a;
    asm("{ .reg .u64 t; cvta.to.shared.u64 t, %1; cvt.u32.u64 %0, t; }" : "=r"(a) : "l"(p));
    return a;
}
__device__ __forceinline__ void cp_async16(uint32_t saddr, const void* g) {
    asm volatile("cp.async.cg.shared.global [%0], [%1], 16;" :: "r"(saddr), "l"(g) : "memory");
}
#define CP_COMMIT()  asm volatile("cp.async.commit_group;" ::: "memory")
#define CP_WAIT1()   asm volatile("cp.async.wait_group 1;" ::: "memory")

__device__ __forceinline__ uint32_t sw128(uint32_t off) {
    return off ^ ((off >> 3) & 0x70);
}
__device__ __forceinline__ void ldsm4(uint32_t& r0, uint32_t& r1, uint32_t& r2, uint32_t& r3,
                                      uint32_t addr) {
    asm volatile("ldmatrix.sync.aligned.m8n8.x4.shared.b16 {%0,%1,%2,%3}, [%4];"
                 : "=r"(r0), "=r"(r1), "=r"(r2), "=r"(r3) : "r"(addr));
}
__device__ __forceinline__ void mma_f16(float* c, const uint32_t* a, const uint32_t* b) {
    asm volatile(
        "mma.sync.aligned.m16n8k16.row.col.f32.f16.f16.f32 "
        "{%0,%1,%2,%3}, {%4,%5,%6,%7}, {%8,%9}, {%0,%1,%2,%3};"
        : "+f"(c[0]), "+f"(c[1]), "+f"(c[2]), "+f"(c[3])
        : "r"(a[0]), "r"(a[1]), "r"(a[2]), "r"(a[3]), "r"(b[0]), "r"(b[1]));
}

// ================= merged prep (proven R15) =================
#define HBLK  128
#define XBLK  4096
#define W1BLK 1024
#define W2BLK 512
#define PREP_GRID (HBLK + XBLK + W1BLK + W2BLK)

__global__ __launch_bounds__(256) void prep_all(
    const float* __restrict__ x, const float* __restrict__ h,
    const float* __restrict__ W1, const float* __restrict__ W2,
    __half* __restrict__ xh, __half* __restrict__ w1, __half* __restrict__ w2)
{
    __shared__ float scs[HDD];
    const int tid  = threadIdx.x;
    const int blk  = blockIdx.x;

    if (blk >= HBLK) {
        const float* src;
        __half* dst;
        size_t base;
        if (blk < HBLK + XBLK) {
            const size_t b = (size_t)(blk - HBLK) * 2048;
#pragma unroll
            for (int j = 0; j < 8; ++j) {
                const size_t idx = b + tid + j * 256;
                const size_t row = idx >> 8, c = idx & 255;
                float4 v = ((const float4*)x)[idx];
                __half2* o = (__half2*)xh;
                o[row * 1024 + c * 2]     = __floats2half2_rn(v.x, v.y);
                o[row * 1024 + c * 2 + 1] = __floats2half2_rn(v.z, v.w);
            }
            return;
        } else if (blk < HBLK + XBLK + W1BLK) {
            src = W1; dst = w1;
            base = (size_t)(blk - HBLK - XBLK) * 1024;
        } else {
            src = W2; dst = w2;
            base = (size_t)(blk - HBLK - XBLK - W1BLK) * 1024;
        }
#pragma unroll
        for (int j = 0; j < 4; ++j) {
            const size_t idx = base + tid + j * 256;
            float4 v = ((const float4*)src)[idx];
            ((__half2*)dst)[idx * 2]     = __floats2half2_rn(v.x, v.y);
            ((__half2*)dst)[idx * 2 + 1] = __floats2half2_rn(v.z, v.w);
        }
        return;
    }

    // ---- h_stats branch ----
    const int wid  = tid >> 5;
    const int lane = tid & 31;
    const int a = blk * 256 + wid * 32;

    scs[tid * 4 + 0] = 0.f; scs[tid * 4 + 1] = 0.f;
    scs[tid * 4 + 2] = 0.f; scs[tid * 4 + 3] = 0.f;
    __syncthreads();

    float cur[32], prev[32], csum[32];
#pragma unroll
    for (int j = 0; j < 32; ++j) csum[j] = 0.f;

    double rs2_loc = 0.0, dh_loc = 0.0;

    for (int r = a; r < a + 32; ++r) {
        float rsum = 0.f;
#pragma unroll
        for (int it2 = 0; it2 < 8; ++it2) {
            const int col = it2 * 128 + lane * 4;
            float4 v = *(const float4*)&h[(size_t)r * HDD + col];
            cur[it2 * 4 + 0] = v.x; cur[it2 * 4 + 1] = v.y;
            cur[it2 * 4 + 2] = v.z; cur[it2 * 4 + 3] = v.w;
            csum[it2 * 4 + 0] += v.x; csum[it2 * 4 + 1] += v.y;
            csum[it2 * 4 + 2] += v.z; csum[it2 * 4 + 3] += v.w;
            rsum += (v.x + v.y) + (v.z + v.w);
            __half2* o = (__half2*)&xh[(size_t)r * DD + PD + col];
            o[0] = __floats2half2_rn(v.x, v.y);
            o[1] = __floats2half2_rn(v.z, v.w);
        }
#pragma unroll
        for (int o = 16; o; o >>= 1) rsum += __shfl_down_sync(0xffffffffu, rsum, o);
        if (lane == 0 && r < NR - 1) rs2_loc += (double)rsum * (double)rsum;

        if (r > a) {
            float d2 = 0.f;
#pragma unroll
            for (int j = 0; j < 32; ++j) {
                float d = cur[j] - prev[j];
                d2 += d * d;
            }
#pragma unroll
            for (int o = 16; o; o >>= 1) d2 += __shfl_down_sync(0xffffffffu, d2, o);
            if (lane == 0) dh_loc += (double)d2;
        }
#pragma unroll
        for (int j = 0; j < 32; ++j) prev[j] = cur[j];
    }

    if (a + 32 < NR) {
        float d2 = 0.f;
#pragma unroll
        for (int it2 = 0; it2 < 8; ++it2) {
            const int col = it2 * 128 + lane * 4;
            float4 v = *(const float4*)&h[(size_t)(a + 32) * HDD + col];
            float d;
            d = v.x - prev[it2 * 4 + 0]; d2 += d * d;
            d = v.y - prev[it2 * 4 + 1]; d2 += d * d;
            d = v.z - prev[it2 * 4 + 2]; d2 += d * d;
            d = v.w - prev[it2 * 4 + 3]; d2 += d * d;
        }
#pragma unroll
        for (int o = 16; o; o >>= 1) d2 += __shfl_down_sync(0xffffffffu, d2, o);
        if (lane == 0) dh_loc += (double)d2;
    }

    if (lane == 0) {
        atomicAdd(&g_rs2, rs2_loc);
        atomicAdd(&g_diffh, dh_loc);
    }

#pragma unroll
    for (int it2 = 0; it2 < 8; ++it2) {
        const int col = it2 * 128 + lane * 4;
        atomicAdd(&scs[col + 0], csum[it2 * 4 + 0]);
        atomicAdd(&scs[col + 1], csum[it2 * 4 + 1]);
        atomicAdd(&scs[col + 2], csum[it2 * 4 + 2]);
        atomicAdd(&scs[col + 3], csum[it2 * 4 + 3]);
    }
    __syncthreads();
#pragma unroll
    for (int j = 0; j < 4; ++j) {
        const int c = tid * 4 + j;
        atomicAdd(&g_musum[c], (double)scs[c]);
    }
}

// ================= fp16 mma.sync GEMM — 128x128 tile, 2 CTAs/SM =================
#define BM 128
#define BN 128
#define BK 64
#define NSTG 3
#define A_BYTES 16384                     // 128 rows x 128B
#define B_BYTES 16384                     // 128 rows x 128B
#define STAGE_BYTES (A_BYTES + B_BYTES)   // 32768
#define GEMM_SMEM (NSTG * STAGE_BYTES)    // 98304

__device__ __forceinline__ void load_stage(
    int j, int tid, int bm, int bn,
    const __half* __restrict__ A, int lda,
    const __half* __restrict__ B, int ldb, uint32_t stg0)
{
    const uint32_t sA = stg0 + (j % NSTG) * STAGE_BYTES;
    const uint32_t sB = sA + A_BYTES;
    const int kg = j << 6;
#pragma unroll
    for (int i = 0; i < 4; ++i) {                 // A: 1024 16B-chunks / 256 thr
        int q = tid + (i << 8);
        int row = q >> 3, c16 = q & 7;
        cp_async16(sA + sw128(row * 128 + c16 * 16),
                   A + (size_t)(bm + row) * lda + kg + (c16 << 3));
    }
#pragma unroll
    for (int i = 0; i < 4; ++i) {                 // B: 1024 chunks
        int q = tid + (i << 8);
        int row = q >> 3, c16 = q & 7;
        cp_async16(sB + sw128(row * 128 + c16 * 16),
                   B + (size_t)(bn + row) * ldb + kg + (c16 << 3));
    }
}

template<bool HALF_OUT, bool FUSE_DX>
__global__ __launch_bounds__(256, 2) void gemm_f16(
    const __half* __restrict__ A, int lda,
    const __half* __restrict__ B, const float* __restrict__ bias,
    void* __restrict__ Cv, int Ncols, int K,
    const float* __restrict__ Xp)
{
    extern __shared__ char smem[];
    const int tid  = threadIdx.x;
    const int wid  = tid >> 5;
    const int lane = tid & 31;
    const int bm = blockIdx.y << 7;       // BM=128
    const int bn = blockIdx.x << 7;       // BN=128
    const uint32_t stg0 = smem_u32(smem);

    const int wm = (wid & 1) << 6;        // warp M offset: 0/64
    const int wn = (wid >> 1) << 5;       // warp N offset: 0..96

    float acc[4][4][4];
#pragma unroll
    for (int i = 0; i < 4; ++i)
#pragma unroll
        for (int j = 0; j < 4; ++j)
#pragma unroll
            for (int r = 0; r < 4; ++r) acc[i][j][r] = 0.f;

    const int nk = K >> 6;                // 32 iterations of BK=64
    load_stage(0, tid, bm, bn, A, lda, B, K, stg0); CP_COMMIT();
    load_stage(1, tid, bm, bn, A, lda, B, K, stg0); CP_COMMIT();

    const int a_row_l = lane & 15;
    const int a_chk_l = lane >> 4;
    const int b_row_l = (lane & 7) + ((lane >> 4) & 1) * 8;
    const int b_chk_l = (lane >> 3) & 1;

    for (int it = 0; it < nk; ++it) {
        CP_WAIT1();
        __syncthreads();                   // single barrier per iteration:
                                           // orders prior LDSM reads of slot it%3
                                           // before next load_stage overwrite

        const int jn = it + 2;
        if (jn < nk) load_stage(jn, tid, bm, bn, A, lda, B, K, stg0);
        CP_COMMIT();

        const uint32_t sA = stg0 + (it % NSTG) * STAGE_BYTES;
        const uint32_t sB = sA + A_BYTES;

#pragma unroll
        for (int q = 0; q < 4; ++q) {
            uint32_t af[4][4], bf[2][4];
#pragma unroll
            for (int t = 0; t < 4; ++t) {
                const int row = wm + t * 16 + a_row_l;
                ldsm4(af[t][0], af[t][1], af[t][2], af[t][3],
                      sA + sw128(row * 128 + q * 32 + a_chk_l * 16));
            }
#pragma unroll
            for (int p = 0; p < 2; ++p) {
                const int row = wn + p * 16 + b_row_l;
                ldsm4(bf[p][0], bf[p][1], bf[p][2], bf[p][3],
                      sB + sw128(row * 128 + q * 32 + b_chk_l * 16));
            }
#pragma unroll
            for (int t = 0; t < 4; ++t)
#pragma unroll
                for (int nt = 0; nt < 4; ++nt)
                    mma_f16(acc[t][nt], af[t], &bf[nt >> 1][(nt & 1) * 2]);
        }
    }

    const int g   = lane >> 2;
    const int ctg = lane & 3;
    float2 bv[4];
#pragma unroll
    for (int nt = 0; nt < 4; ++nt)
        bv[nt] = *(const float2*)&bias[bn + wn + nt * 8 + ctg * 2];

    float dacc = 0.f;

#pragma unroll
    for (int t = 0; t < 4; ++t) {
        const int r0 = bm + wm + t * 16 + g;
#pragma unroll
        for (int nt = 0; nt < 4; ++nt) {
            const int col = bn + wn + nt * 8 + ctg * 2;
            float v00 = fmaxf(acc[t][nt][0] + bv[nt].x, 0.f);
            float v01 = fmaxf(acc[t][nt][1] + bv[nt].y, 0.f);
            float v10 = fmaxf(acc[t][nt][2] + bv[nt].x, 0.f);
            float v11 = fmaxf(acc[t][nt][3] + bv[nt].y, 0.f);
            if (HALF_OUT) {
                __half* C = (__half*)Cv;
                *(__half2*)&C[(size_t)r0 * Ncols + col]       = __floats2half2_rn(v00, v01);
                *(__half2*)&C[(size_t)(r0 + 8) * Ncols + col] = __floats2half2_rn(v10, v11);
            } else {
                float* C = (float*)Cv;
                *(float2*)&C[(size_t)r0 * Ncols + col]       = make_float2(v00, v01);
                *(float2*)&C[(size_t)(r0 + 8) * Ncols + col] = make_float2(v10, v11);
            }
            if (FUSE_DX) {
                if (r0 < NR - 1) {
                    float2 x0 = *(const float2*)&Xp[(size_t)r0 * PD + col];
                    float2 x1 = *(const float2*)&Xp[(size_t)(r0 + 1) * PD + col];
                    float d0 = v00 - (x1.x - x0.x);
                    float d1 = v01 - (x1.y - x0.y);
                    dacc += d0 * d0 + d1 * d1;
                }
                if (r0 + 8 < NR - 1) {
                    float2 x0 = *(const float2*)&Xp[(size_t)(r0 + 8) * PD + col];
                    float2 x1 = *(const float2*)&Xp[(size_t)(r0 + 9) * PD + col];
                    float d0 = v10 - (x1.x - x0.x);
                    float d1 = v11 - (x1.y - x0.y);
                    dacc += d0 * d0 + d1 * d1;
                }
            }
        }
    }

    if (FUSE_DX) {
#pragma unroll
        for (int o = 16; o; o >>= 1) dacc += __shfl_down_sync(0xffffffffu, dacc, o);
        __syncthreads();
        float* red = (float*)smem;
        if (lane == 0) red[wid] = dacc;
        __syncthreads();
        if (tid == 0) {
            float s = 0.f;
#pragma unroll
            for (int i = 0; i < 8; ++i) s += red[i];
            atomicAdd(&g_diffx, (double)s);
        }
    }
}

// ================= finalize =================
__global__ void finalize_kernel(float* __restrict__ out_scalars) {
    const int t = threadIdx.x;
    double mu = g_musum[t] * (1.0 / (double)NR);
    double a = mu, b = mu * mu;
#pragma unroll
    for (int o = 16; o; o >>= 1) {
        a += __shfl_down_sync(0xffffffffu, a, o);
        b += __shfl_down_sync(0xffffffffu, b, o);
    }
    __shared__ double pa[32], pb[32];
    const int w = t >> 5, l = t & 31;
    if (l == 0) { pa[w] = a; pb[w] = b; }
    __syncthreads();
    if (w == 0) {
        a = pa[l];
        b = pb[l];
#pragma unroll
        for (int o = 16; o; o >>= 1) {
            a += __shfl_down_sync(0xffffffffu, a, o);
            b += __shfl_down_sync(0xffffffffu, b, o);
        }
        if (t == 0) {
            const double smu = a, mumu = b;
            const double hd = (double)HDD, nm1 = (double)(NR - 1), eps = 1e-8;
            const double s = g_rs2 / nm1 / (hd * hd);
            const double loss1 = sqrt(g_diffx) / nm1 + sqrt(g_diffh) / nm1;
            const double trS = hd * s - mumu;
            const double detM = (1.0 + s * hd / eps) * (1.0 - mumu / eps)
                              + s * smu * smu / (eps * eps);
            const double logabsdet = hd * log(eps) + log(fabs(detM));
            const double loss = loss1 + 0.5 * (mumu + trS - hd - logabsdet);
            out_scalars[0] = (float)loss1;
            out_scalars[1] = (float)loss;
        }
    }
}

// ================= launch =================
extern "C" void kernel_launch(void* const* d_in, const int* in_sizes, int n_in,
                              void* d_out, int out_size) {
    const float* x  = (const float*)d_in[0];
    const float* h  = (const float*)d_in[1];
    const float* W1 = (const float*)d_in[2];
    const float* b1 = (const float*)d_in[3];
    const float* W2 = (const float*)d_in[4];
    const float* b2 = (const float*)d_in[5];

    float* out     = (float*)d_out;
    float* f       = out;
    float* scalars = out + (size_t)NR * PD;

    __half *a1, *xh, *w1, *w2;
    cudaGetSymbolAddress((void**)&a1, g_a1);
    cudaGetSymbolAddress((void**)&xh, g_xh);
    cudaGetSymbolAddress((void**)&w1, g_w1);
    cudaGetSymbolAddress((void**)&w2, g_w2);

    cudaFuncSetAttribute(gemm_f16<true,  false>, cudaFuncAttributeMaxDynamicSharedMemorySize, GEMM_SMEM);
    cudaFuncSetAttribute(gemm_f16<false, true>,  cudaFuncAttributeMaxDynamicSharedMemorySize, GEMM_SMEM);

    init_kernel<<<4, 256>>>();

    // merged prep: x/h/W1/W2 conversions + h statistics, one launch
    prep_all<<<PREP_GRID, 256>>>(x, h, W1, W2, xh, w1, w2);

    // GEMM1: a1 = relu(xh @ W1^T + b1), fp16 output
    gemm_f16<true, false><<<dim3(DD / BN, NR / BM), 256, GEMM_SMEM>>>(
        xh, DD, w1, b1, a1, DD, DD, nullptr);

    // GEMM2: f = relu(a1 @ W2^T + b2), fp32 output + fused diffx
    gemm_f16<false, true><<<dim3(PD / BN, NR / BM), 256, GEMM_SMEM>>>(
        a1, DD, w2, b2, f, PD, DD, x);

    finalize_kernel<<<1, 1024>>>(scalars);
}